// round 10
// baseline (speedup 1.0000x reference)
#include <cuda_runtime.h>
#include <cstdint>

#define N_  2
#define C_  64
#define H_  256
#define W_  256
#define HW  (H_*W_)
#define HD  128
#define WD  128
#define HWD (HD*WD)
#define KK  25
#define KP  28                      // padded k-vector stride (112B, float4-aligned)
#define CGS28 (N_*HWD*KP)           // per-channel-group partial stride (padded)

// scratch (device globals per allocation-free rule)
__device__ __align__(16) float g_w2[KK*64*9];        // folded weights (25,64,3,3)
__device__ __align__(16) float g_tb[KK*9];           // per-tap folded bias
__device__ __align__(16) float g_part[4*CGS28];      // partial logits (padded), 14.7 MB
__device__ __align__(16) float g_k[N_*HWD*KP];       // softmax weights (n,hd,wd,28)
__device__ __align__(16) float g_reasm[N_*256*HWD];  // 33.5 MB (n,c2,hd,wd)

// cp.async 4B with zero-fill when invalid (src_size=0 -> no memory access, zeros)
__device__ __forceinline__ void cp_async4(uint32_t dst_smem, const void* src, bool valid) {
    int sz = valid ? 4 : 0;
    asm volatile("cp.async.ca.shared.global [%0], [%1], 4, %2;\n"
                 :: "r"(dst_smem), "l"(src), "r"(sz));
}
__device__ __forceinline__ void cp_async_commit() {
    asm volatile("cp.async.commit_group;\n");
}

// ---- packed fp32x2 helpers (sm_103a FFMA2; ptxas never auto-fuses) ----
__device__ __forceinline__ unsigned long long pack2(float lo, float hi) {
    unsigned long long r;
    asm("mov.b64 %0, {%1, %2};" : "=l"(r) : "f"(lo), "f"(hi));
    return r;
}
__device__ __forceinline__ void fma2(unsigned long long& d,
                                     unsigned long long a, unsigned long long b) {
    asm("fma.rn.f32x2 %0, %1, %2, %0;" : "+l"(d) : "l"(a), "l"(b));
}
__device__ __forceinline__ float2 unpack2(unsigned long long v) {
    float lo, hi;
    asm("mov.b64 {%0, %1}, %2;" : "=f"(lo), "=f"(hi) : "l"(v));
    return make_float2(lo, hi);
}

// ---------------------------------------------------------------------------
// Kernel 0: fold down(1x1) into enc(3x3):
//   W2[kk,ci,rs] = sum_c ew[kk,c,rs]*dw[c,ci]
//   TB[kk,rs]    = sum_c ew[kk,c,rs]*db[c]
// ---------------------------------------------------------------------------
__global__ void k_w2(const float* __restrict__ ew,
                     const float* __restrict__ dw,
                     const float* __restrict__ db) {
    __shared__ float sew[576];
    __shared__ float sdb[64];
    __shared__ float sdw[64*64];
    const int kk = blockIdx.x;
    const int t  = threadIdx.x;
    sew[t] = ew[kk*576 + t];
    if (t < 64) sdb[t] = db[t];
    for (int i = t; i < 4096; i += 576) sdw[i] = dw[i];
    __syncthreads();

    const int ci = t / 9, rs = t % 9;
    float s = 0.f;
#pragma unroll 8
    for (int c = 0; c < 64; c++) s += sew[c*9 + rs] * sdw[c*64 + ci];
    g_w2[kk*576 + ci*9 + rs] = s;

    if (t < 9) {
        float s2 = 0.f;
        for (int c = 0; c < 64; c++) s2 += sew[c*9 + t] * sdb[c];
        g_tb[kk*9 + t] = s2;
    }
}

// ---------------------------------------------------------------------------
// Kernel 1: folded 3x3 stride-2 conv x(64ch) -> 25 partial logits.
// Channel-split x4: grid (8,8,8), z = n*4+cg, 16 ch/block, 128 threads.
// NEW: all 16 channels' weights preloaded ONCE (duplicated float2 for f32x2),
// cp.async double-buffered channel staging, f32x2 packed accumulation of the
// thread's two vertical pixels.
// ---------------------------------------------------------------------------
#define ENC_TILE_F (33*36)

__global__ void __launch_bounds__(128) k_enc(const float* __restrict__ x) {
    __shared__ float tile[2][33][36];          // double-buffered input tile
    __shared__ float2 ws2[16][25][9];          // weights, duplicated lanes (28.8KB)
    const int n   = blockIdx.z >> 2;
    const int cg  = blockIdx.z & 3;
    const int hd0 = blockIdx.y * 16;
    const int wd0 = blockIdx.x * 16;
    const int tid = threadIdx.x;               // 128
    const int tx  = tid & 15;
    const int ty  = tid >> 4;                  // 0..7 -> hd pair
    const int c0  = cg * 16;

    // preload all 16 channels' folded weights, duplicated for f32x2
    for (int idx = tid; idx < 16*225; idx += 128) {
        int ci  = idx / 225;
        int rem = idx % 225;                   // kk*9+t
        float v = g_w2[(rem / 9) * 576 + (c0 + ci) * 9 + (rem % 9)];
        ws2[ci][rem / 9][rem % 9] = make_float2(v, v);
    }

    const int h0 = 2 * hd0 - 1;
    const int w0 = 2 * wd0 - 1;
    const float* src = x + (size_t)n * C_ * HW;
    const uint32_t smem_tile = (uint32_t)__cvta_generic_to_shared(&tile[0][0][0]);

    auto stage = [&](int ci, int buf) {
        const float* sc = src + (size_t)(c0 + ci) * HW;
        const uint32_t base = smem_tile + (uint32_t)buf * (ENC_TILE_F * 4);
#pragma unroll
        for (int i = 0; i < 9; i++) {
            int idx = tid + i * 128;
            if (idx < 33*33) {
                int r = idx / 33, cc = idx % 33;
                int h = h0 + r, w = w0 + cc;
                bool ok = (h >= 0 && h < H_ && w >= 0 && w < W_);
                cp_async4(base + (uint32_t)(r * 36 + cc) * 4, sc + h * W_ + w, ok);
            }
        }
        cp_async_commit();
    };

    stage(0, 0);
    stage(1, 1);

    unsigned long long acc2[KK];               // {pixel(2ty), pixel(2ty+1)} packed
#pragma unroll
    for (int kk = 0; kk < KK; kk++) acc2[kk] = 0ULL;

    for (int ci = 0; ci < 16; ci++) {
        if (ci == 15) asm volatile("cp.async.wait_group 0;\n");
        else          asm volatile("cp.async.wait_group 1;\n");
        __syncthreads();                       // buffer ci&1 ready (also ws2 on ci=0)

        const float (*tb)[36] = tile[ci & 1];
        unsigned long long v01[9];
#pragma unroll
        for (int r = 0; r < 3; r++)
#pragma unroll
            for (int s = 0; s < 3; s++)
                v01[r*3+s] = pack2(tb[4*ty + r][2*tx + s],
                                   tb[4*ty + 2 + r][2*tx + s]);

        const unsigned long long* wc =
            (const unsigned long long*)&ws2[ci][0][0];   // 225 dup'd weights
#pragma unroll
        for (int kk = 0; kk < KK; kk++)
#pragma unroll
            for (int t = 0; t < 9; t++)
                fma2(acc2[kk], wc[kk*9 + t], v01[t]);

        if (ci < 14) {
            __syncthreads();                   // all reads of buffer ci&1 done
            stage(ci + 2, ci & 1);
        }
    }

    const int wd = wd0 + tx;
    float* dst0 = g_part + cg * CGS28 + ((size_t)((n * HD + hd0 + 2*ty) * WD + wd)) * KP;
    float* dst1 = g_part + cg * CGS28 + ((size_t)((n * HD + hd0 + 2*ty + 1) * WD + wd)) * KP;
#pragma unroll
    for (int kk = 0; kk < KK; kk++) {
        float2 r = unpack2(acc2[kk]);
        dst0[kk] = r.x;
        dst1[kk] = r.y;
    }
}

// ---------------------------------------------------------------------------
// Kernel 2: sum 4 partials + bias (padding-aware tap bias) + softmax.
// float4 loads/stores on the padded 28-float layout.
// ---------------------------------------------------------------------------
__global__ void __launch_bounds__(256) k_softmax(const float* __restrict__ eb) {
    __shared__ float stb[225];
    __shared__ float seb[25];
    const int tid = threadIdx.x;
    if (tid < 225) stb[tid] = g_tb[tid];
    if (tid < 25)  seb[tid] = eb[tid];
    __syncthreads();

    const int pix = blockIdx.x * 256 + tid;           // 32768 pixels
    const int wd = pix & 127;
    const int hd = (pix >> 7) & 127;

    // tap validity: only top/left edge clips (stride2, pad1, k=3)
    const float r0 = (hd != 0) ? 1.f : 0.f;
    const float s0 = (wd != 0) ? 1.f : 0.f;
    float m9[9];
    m9[0] = r0 * s0; m9[1] = r0; m9[2] = r0;
    m9[3] = s0;      m9[4] = 1.f; m9[5] = 1.f;
    m9[6] = s0;      m9[7] = 1.f; m9[8] = 1.f;

    const float4* p0 = (const float4*)(g_part + (size_t)pix * KP);
    const float4* p1 = (const float4*)(g_part + CGS28   + (size_t)pix * KP);
    const float4* p2 = (const float4*)(g_part + 2*CGS28 + (size_t)pix * KP);
    const float4* p3 = (const float4*)(g_part + 3*CGS28 + (size_t)pix * KP);
    float a[28];
#pragma unroll
    for (int i = 0; i < 7; i++) {
        float4 v0 = p0[i], v1 = p1[i], v2 = p2[i], v3 = p3[i];
        a[4*i+0] = v0.x + v1.x + v2.x + v3.x;
        a[4*i+1] = v0.y + v1.y + v2.y + v3.y;
        a[4*i+2] = v0.z + v1.z + v2.z + v3.z;
        a[4*i+3] = v0.w + v1.w + v2.w + v3.w;
    }

    float lg[28];
#pragma unroll
    for (int kk = 0; kk < KK; kk++) {
        float v = a[kk] + seb[kk];
#pragma unroll
        for (int t = 0; t < 9; t++) v += m9[t] * stb[kk*9 + t];
        lg[kk] = v;
    }

    float mx = lg[0];
#pragma unroll
    for (int kk = 1; kk < KK; kk++) mx = fmaxf(mx, lg[kk]);
    float sum = 0.f;
#pragma unroll
    for (int kk = 0; kk < KK; kk++) { lg[kk] = expf(lg[kk] - mx); sum += lg[kk]; }
    float inv = 1.f / sum;
#pragma unroll
    for (int kk = 0; kk < KK; kk++) lg[kk] *= inv;
    lg[25] = 0.f; lg[26] = 0.f; lg[27] = 0.f;

    float4* dst = (float4*)(g_k + (size_t)pix * KP);
#pragma unroll
    for (int i = 0; i < 7; i++)
        dst[i] = make_float4(lg[4*i], lg[4*i+1], lg[4*i+2], lg[4*i+3]);
}

// ---------------------------------------------------------------------------
// Kernel 3: weighted 5x5 reassembly, cp.async double-buffered pipeline.
// (unchanged from R9 — 44us, near LDS floor)
// ---------------------------------------------------------------------------
#define XT_ROWSZ 260
#define XT_BUF   (4*6*XT_ROWSZ)          // floats per buffer = 6240

__global__ void __launch_bounds__(256, 2) k_reasm(const float* __restrict__ x) {
    extern __shared__ float xs[];        // xs[2][4][6][260]
    const int n   = blockIdx.z;
    const int cg  = blockIdx.y;          // 0..15 -> channels cg*4..cg*4+3
    const int hd0 = blockIdx.x * 4;
    const int tid = threadIdx.x;         // 256

    const int wd  = tid & 127;
    const int ph  = tid >> 7;            // 0..1
    const int hdA = hd0 + ph;            // xt rows 0..4
    const int hdB = hd0 + ph + 2;        // xt rows 1..5 (same parity)
    const int col0 = ((hdA & 1) << 7) + wd;
    const int rbase = (hd0 >> 1) - 2;

    const uint32_t smem_u32 = (uint32_t)__cvta_generic_to_shared(xs);

    // load both pixels' 25 softmax weights once (7 LDG.128 each)
    float kwA[25], kwB[25];
    {
        const float4* kpA = (const float4*)(g_k + (size_t)((n * HD + hdA) * WD + wd) * KP);
        const float4* kpB = (const float4*)(g_k + (size_t)((n * HD + hdB) * WD + wd) * KP);
        float tA[28], tB[28];
#pragma unroll
        for (int i = 0; i < 7; i++) {
            float4 va = kpA[i], vb = kpB[i];
            tA[4*i] = va.x; tA[4*i+1] = va.y; tA[4*i+2] = va.z; tA[4*i+3] = va.w;
            tB[4*i] = vb.x; tB[4*i+1] = vb.y; tB[4*i+2] = vb.z; tB[4*i+3] = vb.w;
        }
#pragma unroll
        for (int kk = 0; kk < KK; kk++) { kwA[kk] = tA[kk]; kwB[kk] = tB[kk]; }
    }

    const float* xn = x + (size_t)n * C_ * HW;

    auto stage = [&](int ci, int buf) {
        const float* src = xn + (size_t)(cg * 4 + ci) * HW;
        const uint32_t base = smem_u32 + (uint32_t)buf * (XT_BUF * 4);
#pragma unroll
        for (int qr = 0; qr < 24; qr++) {
            const int q  = qr / 6;
            const int rl = qr % 6;
            const int h = q * 64 + rbase + rl;
            const bool hv = (h >= 0) && (h < H_);
            const float* rowp = src + h * W_;
            const int w = tid - 2;
            cp_async4(base + (uint32_t)(qr * XT_ROWSZ + tid) * 4,
                      rowp + w, hv && (w >= 0));
            if (tid < 4) {
                const int w2 = 254 + tid;
                cp_async4(base + (uint32_t)(qr * XT_ROWSZ + 256 + tid) * 4,
                          rowp + w2, hv && (w2 < W_));
            }
        }
        cp_async_commit();
    };

    stage(0, 0);
    stage(1, 1);

#pragma unroll
    for (int ci = 0; ci < 4; ci++) {
        if (ci == 3) asm volatile("cp.async.wait_group 0;\n");
        else         asm volatile("cp.async.wait_group 1;\n");
        __syncthreads();

        const float* xb = xs + (ci & 1) * XT_BUF;
        const int c = cg * 4 + ci;

#pragma unroll
        for (int q = 0; q < 4; q++) {
            float sA = 0.f, sB = 0.f;
            const float* qb = xb + q * (6 * XT_ROWSZ) + col0;
#pragma unroll
            for (int dj = 0; dj < 5; dj++) {
                float v[6];
#pragma unroll
                for (int r = 0; r < 6; r++) v[r] = qb[r * XT_ROWSZ + dj];
#pragma unroll
                for (int di = 0; di < 5; di++) {
                    sA += kwA[di * 5 + dj] * v[di];
                    sB += kwB[di * 5 + dj] * v[di + 1];
                }
            }
            g_reasm[(size_t)((n * 256 + c * 4 + q) * HD + hdA) * WD + wd] = sA;
            g_reasm[(size_t)((n * 256 + c * 4 + q) * HD + hdB) * WD + wd] = sB;
        }

        if (ci < 2) {
            __syncthreads();
            stage(ci + 2, ci & 1);
        }
    }
}

// ---------------------------------------------------------------------------
// Kernel 4: 1x1 conv 256->64, f32x2 packed: the two 64-px halves share every
// weight -> pack {xa,xb}, weights dup'd in smem (Wr2 padded [64][33] float2,
// conflict-free). 16 FFMA2 + 4 packs per kc instead of 32 FFMA.
// ---------------------------------------------------------------------------
__global__ void __launch_bounds__(256) k_out(const float* __restrict__ w,
                                             const float* __restrict__ b,
                                             float* __restrict__ out) {
    __shared__ float  Xs[32][128];    // [k][pixel]
    __shared__ float2 Wr2[64][33];    // [cout][k], duplicated lanes, padded
    const int tid  = threadIdx.x;
    const int n    = blockIdx.x >> 7;          // 128 pixel-blocks per n
    const int p0   = (blockIdx.x & 127) << 7;  // 128 pixels
    const int px16 = tid & 15;                 // pixel quad base
    const int chg  = tid >> 4;                 // cout quad (0..15)

    unsigned long long accp[4][4];             // [pi][co], {h0,h1} packed
#pragma unroll
    for (int co = 0; co < 4; co++) {
        float bv = b[chg * 4 + co];
#pragma unroll
        for (int pi = 0; pi < 4; pi++) accp[pi][co] = pack2(bv, bv);
    }

    for (int kb = 0; kb < 8; kb++) {
        __syncthreads();
#pragma unroll
        for (int i = 0; i < 4; i++) {
            int f   = tid + i * 256;
            int row = f >> 5;
            int col = (f & 31) * 4;
            float4 v = *(const float4*)&g_reasm[(size_t)(n*256 + kb*32 + row) * HWD + p0 + col];
            *(float4*)&Xs[row][col] = v;
        }
#pragma unroll
        for (int i = 0; i < 2; i++) {
            int f    = tid + i * 256;
            int cout = f >> 3;
            int kg   = f & 7;
            float4 v = *(const float4*)&w[cout * 256 + kb * 32 + kg * 4];
            Wr2[cout][kg*4+0] = make_float2(v.x, v.x);
            Wr2[cout][kg*4+1] = make_float2(v.y, v.y);
            Wr2[cout][kg*4+2] = make_float2(v.z, v.z);
            Wr2[cout][kg*4+3] = make_float2(v.w, v.w);
        }
        __syncthreads();

#pragma unroll 4
        for (int kc = 0; kc < 32; kc++) {
            float4 xa = *(const float4*)&Xs[kc][px16 * 4];
            float4 xb = *(const float4*)&Xs[kc][64 + px16 * 4];
            unsigned long long xp[4];
            xp[0] = pack2(xa.x, xb.x);
            xp[1] = pack2(xa.y, xb.y);
            xp[2] = pack2(xa.z, xb.z);
            xp[3] = pack2(xa.w, xb.w);
            unsigned long long w0 = *(const unsigned long long*)&Wr2[chg*4+0][kc];
            unsigned long long w1 = *(const unsigned long long*)&Wr2[chg*4+1][kc];
            unsigned long long w2 = *(const unsigned long long*)&Wr2[chg*4+2][kc];
            unsigned long long w3 = *(const unsigned long long*)&Wr2[chg*4+3][kc];
#pragma unroll
            for (int pi = 0; pi < 4; pi++) {
                fma2(accp[pi][0], xp[pi], w0);
                fma2(accp[pi][1], xp[pi], w1);
                fma2(accp[pi][2], xp[pi], w2);
                fma2(accp[pi][3], xp[pi], w3);
            }
        }
    }

#pragma unroll
    for (int co = 0; co < 4; co++) {
        int cg = chg * 4 + co;
        float2 r0 = unpack2(accp[0][co]);
        float2 r1 = unpack2(accp[1][co]);
        float2 r2 = unpack2(accp[2][co]);
        float2 r3 = unpack2(accp[3][co]);
        *(float4*)&out[(size_t)(n*64 + cg) * HWD + p0 + px16*4] =
            make_float4(r0.x, r1.x, r2.x, r3.x);
        *(float4*)&out[(size_t)(n*64 + cg) * HWD + p0 + 64 + px16*4] =
            make_float4(r0.y, r1.y, r2.y, r3.y);
    }
}

// ---------------------------------------------------------------------------
extern "C" void kernel_launch(void* const* d_in, const int* in_sizes, int n_in,
                              void* d_out, int out_size) {
    const float* x      = (const float*)d_in[0];
    const float* down_w = (const float*)d_in[1];
    const float* down_b = (const float*)d_in[2];
    const float* enc_w  = (const float*)d_in[3];
    const float* enc_b  = (const float*)d_in[4];
    const float* out_w  = (const float*)d_in[5];
    const float* out_b  = (const float*)d_in[6];
    float* out = (float*)d_out;

    static bool attr_set = false;
    if (!attr_set) {
        cudaFuncSetAttribute(k_reasm, cudaFuncAttributeMaxDynamicSharedMemorySize,
                             2 * XT_BUF * 4);
        attr_set = true;
    }

    k_w2<<<25, 576>>>(enc_w, down_w, down_b);

    dim3 g1(8, 8, 8);                 // z = n*4 + channel-group
    k_enc<<<g1, 128>>>(x);

    k_softmax<<<128, 256>>>(enc_b);

    dim3 g3(32, 16, 2);               // hd-tiles x c-groups(4ch) x n
    k_reasm<<<g3, 256, 2 * XT_BUF * 4>>>(x);

    k_out<<<256, 256>>>(out_w, out_b, out);
}

// round 12
// speedup vs baseline: 1.0263x; 1.0263x over previous
#include <cuda_runtime.h>
#include <cstdint>

#define N_  2
#define C_  64
#define H_  256
#define W_  256
#define HW  (H_*W_)
#define HD  128
#define WD  128
#define HWD (HD*WD)
#define KK  25
#define KP  28                      // padded k-vector stride (112B, float4-aligned)
#define CGS28 (N_*HWD*KP)           // per-channel-group partial stride (padded)

// scratch (device globals per allocation-free rule)
__device__ __align__(16) float2 g_w2d[C_*KK*9];      // folded weights, dup'd lanes, [ci][kk][t]
__device__ __align__(16) float g_tb[KK*9];           // per-tap folded bias
__device__ __align__(16) float g_part[4*CGS28];      // partial logits (padded), 14.7 MB
__device__ __align__(16) float g_k[N_*HWD*KP];       // softmax weights (n,hd,wd,28)
__device__ __align__(16) float g_reasm[N_*256*HWD];  // 33.5 MB (n,c2,hd,wd)

// cp.async 4B with zero-fill when invalid (src_size=0 -> no memory access, zeros)
__device__ __forceinline__ void cp_async4(uint32_t dst_smem, const void* src, bool valid) {
    int sz = valid ? 4 : 0;
    asm volatile("cp.async.ca.shared.global [%0], [%1], 4, %2;\n"
                 :: "r"(dst_smem), "l"(src), "r"(sz));
}
__device__ __forceinline__ void cp_async8(uint32_t dst_smem, const void* src) {
    asm volatile("cp.async.ca.shared.global [%0], [%1], 8;\n"
                 :: "r"(dst_smem), "l"(src));
}
__device__ __forceinline__ void cp_async_commit() {
    asm volatile("cp.async.commit_group;\n");
}

// ---- packed fp32x2 helpers (sm_103a FFMA2; ptxas never auto-fuses) ----
__device__ __forceinline__ unsigned long long pack2(float lo, float hi) {
    unsigned long long r;
    asm("mov.b64 %0, {%1, %2};" : "=l"(r) : "f"(lo), "f"(hi));
    return r;
}
__device__ __forceinline__ void fma2(unsigned long long& d,
                                     unsigned long long a, unsigned long long b) {
    asm("fma.rn.f32x2 %0, %1, %2, %0;" : "+l"(d) : "l"(a), "l"(b));
}
__device__ __forceinline__ float2 unpack2(unsigned long long v) {
    float lo, hi;
    asm("mov.b64 {%0, %1}, %2;" : "=f"(lo), "=f"(hi) : "l"(v));
    return make_float2(lo, hi);
}

// ---------------------------------------------------------------------------
// Kernel 0: fold down(1x1) into enc(3x3):
//   W2[kk,ci,rs] = sum_c ew[kk,c,rs]*dw[c,ci]  -> stored dup'd as g_w2d[ci][kk][rs]
//   TB[kk,rs]    = sum_c ew[kk,c,rs]*db[c]
// ---------------------------------------------------------------------------
__global__ void k_w2(const float* __restrict__ ew,
                     const float* __restrict__ dw,
                     const float* __restrict__ db) {
    __shared__ float sew[576];
    __shared__ float sdb[64];
    __shared__ float sdw[64*64];
    const int kk = blockIdx.x;
    const int t  = threadIdx.x;
    sew[t] = ew[kk*576 + t];
    if (t < 64) sdb[t] = db[t];
    for (int i = t; i < 4096; i += 576) sdw[i] = dw[i];
    __syncthreads();

    const int ci = t / 9, rs = t % 9;
    float s = 0.f;
#pragma unroll 8
    for (int c = 0; c < 64; c++) s += sew[c*9 + rs] * sdw[c*64 + ci];
    g_w2d[(ci * KK + kk) * 9 + rs] = make_float2(s, s);   // per-channel contiguous

    if (t < 9) {
        float s2 = 0.f;
        for (int c = 0; c < 64; c++) s2 += sew[c*9 + t] * sdb[c];
        g_tb[kk*9 + t] = s2;
    }
}

// ---------------------------------------------------------------------------
// Kernel 1: folded 3x3 stride-2 conv x(64ch) -> 25 partial logits.
// Channel-split x4: grid (8,8,8), z = n*4+cg, 16 ch/block, 128 threads.
// Double-buffered cp.async staging of BOTH the input tile and the per-channel
// dup'd weight slice (small smem: 9.5KB + 3.6KB -> high occupancy, unlike R10's
// 16-channel 28.8KB table). FFMA2 packed accumulation of 2 vertical pixels.
// ---------------------------------------------------------------------------
#define ENC_TILE_F (33*36)

__global__ void __launch_bounds__(128) k_enc(const float* __restrict__ x) {
    __shared__ float  tile[2][33][36];         // 9504 B
    __shared__ float2 wsd[2][25][9];           // 3600 B, dup'd weights per channel
    const int n   = blockIdx.z >> 2;
    const int cg  = blockIdx.z & 3;
    const int hd0 = blockIdx.y * 16;
    const int wd0 = blockIdx.x * 16;
    const int tid = threadIdx.x;               // 128
    const int tx  = tid & 15;
    const int ty  = tid >> 4;                  // 0..7 -> hd pair
    const int c0  = cg * 16;

    const int h0 = 2 * hd0 - 1;
    const int w0 = 2 * wd0 - 1;
    const float* src = x + (size_t)n * C_ * HW;
    const uint32_t smem_tile = (uint32_t)__cvta_generic_to_shared(&tile[0][0][0]);
    const uint32_t smem_wsd  = (uint32_t)__cvta_generic_to_shared(&wsd[0][0][0]);

    auto stage = [&](int ci, int buf) {
        const float* sc = src + (size_t)(c0 + ci) * HW;
        const uint32_t tbase = smem_tile + (uint32_t)buf * (ENC_TILE_F * 4);
#pragma unroll
        for (int i = 0; i < 9; i++) {
            int idx = tid + i * 128;
            if (idx < 33*33) {
                int r = idx / 33, cc = idx % 33;
                int h = h0 + r, w = w0 + cc;
                bool ok = (h >= 0 && h < H_ && w >= 0 && w < W_);
                cp_async4(tbase + (uint32_t)(r * 36 + cc) * 4, sc + h * W_ + w, ok);
            }
        }
        const float2* wsrc = g_w2d + (size_t)(c0 + ci) * (KK * 9);
        const uint32_t wbase = smem_wsd + (uint32_t)buf * (KK * 9 * 8);
        cp_async8(wbase + (uint32_t)tid * 8, wsrc + tid);
        if (tid + 128 < 225)
            cp_async8(wbase + (uint32_t)(tid + 128) * 8, wsrc + tid + 128);
        cp_async_commit();
    };

    stage(0, 0);
    stage(1, 1);

    unsigned long long acc2[KK];               // {pixel(2ty), pixel(2ty+1)} packed
#pragma unroll
    for (int kk = 0; kk < KK; kk++) acc2[kk] = 0ULL;

    for (int ci = 0; ci < 16; ci++) {
        if (ci == 15) asm volatile("cp.async.wait_group 0;\n");
        else          asm volatile("cp.async.wait_group 1;\n");
        __syncthreads();                       // buffer ci&1 (tile + weights) ready

        const float (*tb)[36] = tile[ci & 1];
        unsigned long long v01[9];
#pragma unroll
        for (int r = 0; r < 3; r++)
#pragma unroll
            for (int s = 0; s < 3; s++)
                v01[r*3+s] = pack2(tb[4*ty + r][2*tx + s],
                                   tb[4*ty + 2 + r][2*tx + s]);

        const unsigned long long* wc =
            (const unsigned long long*)&wsd[ci & 1][0][0];   // 225 dup'd weights
#pragma unroll
        for (int kk = 0; kk < KK; kk++)
#pragma unroll
            for (int t = 0; t < 9; t++)
                fma2(acc2[kk], wc[kk*9 + t], v01[t]);

        if (ci < 14) {
            __syncthreads();                   // all reads of buffer ci&1 done
            stage(ci + 2, ci & 1);
        }
    }

    const int wd = wd0 + tx;
    float* dst0 = g_part + cg * CGS28 + ((size_t)((n * HD + hd0 + 2*ty) * WD + wd)) * KP;
    float* dst1 = g_part + cg * CGS28 + ((size_t)((n * HD + hd0 + 2*ty + 1) * WD + wd)) * KP;
#pragma unroll
    for (int kk = 0; kk < KK; kk++) {
        float2 r = unpack2(acc2[kk]);
        dst0[kk] = r.x;
        dst1[kk] = r.y;
    }
}

// ---------------------------------------------------------------------------
// Kernel 2: sum 4 partials + bias (padding-aware tap bias) + softmax.
// float4 loads/stores on the padded 28-float layout.
// ---------------------------------------------------------------------------
__global__ void __launch_bounds__(256) k_softmax(const float* __restrict__ eb) {
    __shared__ float stb[225];
    __shared__ float seb[25];
    const int tid = threadIdx.x;
    if (tid < 225) stb[tid] = g_tb[tid];
    if (tid < 25)  seb[tid] = eb[tid];
    __syncthreads();

    const int pix = blockIdx.x * 256 + tid;           // 32768 pixels
    const int wd = pix & 127;
    const int hd = (pix >> 7) & 127;

    // tap validity: only top/left edge clips (stride2, pad1, k=3)
    const float r0 = (hd != 0) ? 1.f : 0.f;
    const float s0 = (wd != 0) ? 1.f : 0.f;
    float m9[9];
    m9[0] = r0 * s0; m9[1] = r0; m9[2] = r0;
    m9[3] = s0;      m9[4] = 1.f; m9[5] = 1.f;
    m9[6] = s0;      m9[7] = 1.f; m9[8] = 1.f;

    const float4* p0 = (const float4*)(g_part + (size_t)pix * KP);
    const float4* p1 = (const float4*)(g_part + CGS28   + (size_t)pix * KP);
    const float4* p2 = (const float4*)(g_part + 2*CGS28 + (size_t)pix * KP);
    const float4* p3 = (const float4*)(g_part + 3*CGS28 + (size_t)pix * KP);
    float a[28];
#pragma unroll
    for (int i = 0; i < 7; i++) {
        float4 v0 = p0[i], v1 = p1[i], v2 = p2[i], v3 = p3[i];
        a[4*i+0] = v0.x + v1.x + v2.x + v3.x;
        a[4*i+1] = v0.y + v1.y + v2.y + v3.y;
        a[4*i+2] = v0.z + v1.z + v2.z + v3.z;
        a[4*i+3] = v0.w + v1.w + v2.w + v3.w;
    }

    float lg[28];
#pragma unroll
    for (int kk = 0; kk < KK; kk++) {
        float v = a[kk] + seb[kk];
#pragma unroll
        for (int t = 0; t < 9; t++) v += m9[t] * stb[kk*9 + t];
        lg[kk] = v;
    }

    float mx = lg[0];
#pragma unroll
    for (int kk = 1; kk < KK; kk++) mx = fmaxf(mx, lg[kk]);
    float sum = 0.f;
#pragma unroll
    for (int kk = 0; kk < KK; kk++) { lg[kk] = expf(lg[kk] - mx); sum += lg[kk]; }
    float inv = 1.f / sum;
#pragma unroll
    for (int kk = 0; kk < KK; kk++) lg[kk] *= inv;
    lg[25] = 0.f; lg[26] = 0.f; lg[27] = 0.f;

    float4* dst = (float4*)(g_k + (size_t)pix * KP);
#pragma unroll
    for (int i = 0; i < 7; i++)
        dst[i] = make_float4(lg[4*i], lg[4*i+1], lg[4*i+2], lg[4*i+3]);
}

// ---------------------------------------------------------------------------
// Kernel 3: weighted 5x5 reassembly, cp.async double-buffered pipeline.
// (unchanged — 44us, near LDS floor)
// ---------------------------------------------------------------------------
#define XT_ROWSZ 260
#define XT_BUF   (4*6*XT_ROWSZ)          // floats per buffer = 6240

__global__ void __launch_bounds__(256, 2) k_reasm(const float* __restrict__ x) {
    extern __shared__ float xs[];        // xs[2][4][6][260]
    const int n   = blockIdx.z;
    const int cg  = blockIdx.y;          // 0..15 -> channels cg*4..cg*4+3
    const int hd0 = blockIdx.x * 4;
    const int tid = threadIdx.x;         // 256

    const int wd  = tid & 127;
    const int ph  = tid >> 7;            // 0..1
    const int hdA = hd0 + ph;            // xt rows 0..4
    const int hdB = hd0 + ph + 2;        // xt rows 1..5 (same parity)
    const int col0 = ((hdA & 1) << 7) + wd;
    const int rbase = (hd0 >> 1) - 2;

    const uint32_t smem_u32 = (uint32_t)__cvta_generic_to_shared(xs);

    // load both pixels' 25 softmax weights once (7 LDG.128 each)
    float kwA[25], kwB[25];
    {
        const float4* kpA = (const float4*)(g_k + (size_t)((n * HD + hdA) * WD + wd) * KP);
        const float4* kpB = (const float4*)(g_k + (size_t)((n * HD + hdB) * WD + wd) * KP);
        float tA[28], tB[28];
#pragma unroll
        for (int i = 0; i < 7; i++) {
            float4 va = kpA[i], vb = kpB[i];
            tA[4*i] = va.x; tA[4*i+1] = va.y; tA[4*i+2] = va.z; tA[4*i+3] = va.w;
            tB[4*i] = vb.x; tB[4*i+1] = vb.y; tB[4*i+2] = vb.z; tB[4*i+3] = vb.w;
        }
#pragma unroll
        for (int kk = 0; kk < KK; kk++) { kwA[kk] = tA[kk]; kwB[kk] = tB[kk]; }
    }

    const float* xn = x + (size_t)n * C_ * HW;

    auto stage = [&](int ci, int buf) {
        const float* src = xn + (size_t)(cg * 4 + ci) * HW;
        const uint32_t base = smem_u32 + (uint32_t)buf * (XT_BUF * 4);
#pragma unroll
        for (int qr = 0; qr < 24; qr++) {
            const int q  = qr / 6;
            const int rl = qr % 6;
            const int h = q * 64 + rbase + rl;
            const bool hv = (h >= 0) && (h < H_);
            const float* rowp = src + h * W_;
            const int w = tid - 2;
            cp_async4(base + (uint32_t)(qr * XT_ROWSZ + tid) * 4,
                      rowp + w, hv && (w >= 0));
            if (tid < 4) {
                const int w2 = 254 + tid;
                cp_async4(base + (uint32_t)(qr * XT_ROWSZ + 256 + tid) * 4,
                          rowp + w2, hv && (w2 < W_));
            }
        }
        cp_async_commit();
    };

    stage(0, 0);
    stage(1, 1);

#pragma unroll
    for (int ci = 0; ci < 4; ci++) {
        if (ci == 3) asm volatile("cp.async.wait_group 0;\n");
        else         asm volatile("cp.async.wait_group 1;\n");
        __syncthreads();

        const float* xb = xs + (ci & 1) * XT_BUF;
        const int c = cg * 4 + ci;

#pragma unroll
        for (int q = 0; q < 4; q++) {
            float sA = 0.f, sB = 0.f;
            const float* qb = xb + q * (6 * XT_ROWSZ) + col0;
#pragma unroll
            for (int dj = 0; dj < 5; dj++) {
                float v[6];
#pragma unroll
                for (int r = 0; r < 6; r++) v[r] = qb[r * XT_ROWSZ + dj];
#pragma unroll
                for (int di = 0; di < 5; di++) {
                    sA += kwA[di * 5 + dj] * v[di];
                    sB += kwB[di * 5 + dj] * v[di + 1];
                }
            }
            g_reasm[(size_t)((n * 256 + c * 4 + q) * HD + hdA) * WD + wd] = sA;
            g_reasm[(size_t)((n * 256 + c * 4 + q) * HD + hdB) * WD + wd] = sB;
        }

        if (ci < 2) {
            __syncthreads();
            stage(ci + 2, ci & 1);
        }
    }
}

// ---------------------------------------------------------------------------
// Kernel 4: 1x1 conv 256->64, f32x2 packed (two 64-px halves share weights).
// ---------------------------------------------------------------------------
__global__ void __launch_bounds__(256) k_out(const float* __restrict__ w,
                                             const float* __restrict__ b,
                                             float* __restrict__ out) {
    __shared__ float  Xs[32][128];    // [k][pixel]
    __shared__ float2 Wr2[64][33];    // [cout][k], duplicated lanes, padded
    const int tid  = threadIdx.x;
    const int n    = blockIdx.x >> 7;          // 128 pixel-blocks per n
    const int p0   = (blockIdx.x & 127) << 7;  // 128 pixels
    const int px16 = tid & 15;                 // pixel quad base
    const int chg  = tid >> 4;                 // cout quad (0..15)

    unsigned long long accp[4][4];             // [pi][co], {h0,h1} packed
#pragma unroll
    for (int co = 0; co < 4; co++) {
        float bv = b[chg * 4 + co];
#pragma unroll
        for (int pi = 0; pi < 4; pi++) accp[pi][co] = pack2(bv, bv);
    }

    for (int kb = 0; kb < 8; kb++) {
        __syncthreads();
#pragma unroll
        for (int i = 0; i < 4; i++) {
            int f   = tid + i * 256;
            int row = f >> 5;
            int col = (f & 31) * 4;
            float4 v = *(const float4*)&g_reasm[(size_t)(n*256 + kb*32 + row) * HWD + p0 + col];
            *(float4*)&Xs[row][col] = v;
        }
#pragma unroll
        for (int i = 0; i < 2; i++) {
            int f    = tid + i * 256;
            int cout = f >> 3;
            int kg   = f & 7;
            float4 v = *(const float4*)&w[cout * 256 + kb * 32 + kg * 4];
            Wr2[cout][kg*4+0] = make_float2(v.x, v.x);
            Wr2[cout][kg*4+1] = make_float2(v.y, v.y);
            Wr2[cout][kg*4+2] = make_float2(v.z, v.z);
            Wr2[cout][kg*4+3] = make_float2(v.w, v.w);
        }
        __syncthreads();

#pragma unroll 4
        for (int kc = 0; kc < 32; kc++) {
            float4 xa = *(const float4*)&Xs[kc][px16 * 4];
            float4 xb = *(const float4*)&Xs[kc][64 + px16 * 4];
            unsigned long long xp[4];
            xp[0] = pack2(xa.x, xb.x);
            xp[1] = pack2(xa.y, xb.y);
            xp[2] = pack2(xa.z, xb.z);
            xp[3] = pack2(xa.w, xb.w);
            unsigned long long w0 = *(const unsigned long long*)&Wr2[chg*4+0][kc];
            unsigned long long w1 = *(const unsigned long long*)&Wr2[chg*4+1][kc];
            unsigned long long w2 = *(const unsigned long long*)&Wr2[chg*4+2][kc];
            unsigned long long w3 = *(const unsigned long long*)&Wr2[chg*4+3][kc];
#pragma unroll
            for (int pi = 0; pi < 4; pi++) {
                fma2(accp[pi][0], xp[pi], w0);
                fma2(accp[pi][1], xp[pi], w1);
                fma2(accp[pi][2], xp[pi], w2);
                fma2(accp[pi][3], xp[pi], w3);
            }
        }
    }

#pragma unroll
    for (int co = 0; co < 4; co++) {
        int cg = chg * 4 + co;
        float2 r0 = unpack2(accp[0][co]);
        float2 r1 = unpack2(accp[1][co]);
        float2 r2 = unpack2(accp[2][co]);
        float2 r3 = unpack2(accp[3][co]);
        *(float4*)&out[(size_t)(n*64 + cg) * HWD + p0 + px16*4] =
            make_float4(r0.x, r1.x, r2.x, r3.x);
        *(float4*)&out[(size_t)(n*64 + cg) * HWD + p0 + 64 + px16*4] =
            make_float4(r0.y, r1.y, r2.y, r3.y);
    }
}

// ---------------------------------------------------------------------------
extern "C" void kernel_launch(void* const* d_in, const int* in_sizes, int n_in,
                              void* d_out, int out_size) {
    const float* x      = (const float*)d_in[0];
    const float* down_w = (const float*)d_in[1];
    const float* down_b = (const float*)d_in[2];
    const float* enc_w  = (const float*)d_in[3];
    const float* enc_b  = (const float*)d_in[4];
    const float* out_w  = (const float*)d_in[5];
    const float* out_b  = (const float*)d_in[6];
    float* out = (float*)d_out;

    static bool attr_set = false;
    if (!attr_set) {
        cudaFuncSetAttribute(k_reasm, cudaFuncAttributeMaxDynamicSharedMemorySize,
                             2 * XT_BUF * 4);
        attr_set = true;
    }

    k_w2<<<25, 576>>>(enc_w, down_w, down_b);

    dim3 g1(8, 8, 8);                 // z = n*4 + channel-group
    k_enc<<<g1, 128>>>(x);

    k_softmax<<<128, 256>>>(enc_b);

    dim3 g3(32, 16, 2);               // hd-tiles x c-groups(4ch) x n
    k_reasm<<<g3, 256, 2 * XT_BUF * 4>>>(x);

    k_out<<<256, 256>>>(out_w, out_b, out);
}

// round 13
// speedup vs baseline: 1.0779x; 1.0504x over previous
#include <cuda_runtime.h>
#include <cstdint>

#define N_  2
#define C_  64
#define H_  256
#define W_  256
#define HW  (H_*W_)
#define HD  128
#define WD  128
#define HWD (HD*WD)
#define KK  25
#define KP  28                      // padded k-vector stride (112B, float4-aligned)
#define CGS28 (N_*HWD*KP)           // per-channel-group partial stride (padded)

// scratch (device globals per allocation-free rule)
__device__ __align__(16) float2 g_w2d[C_*KK*9];      // folded enc weights, dup'd, [ci][kk][t]
__device__ __align__(16) float g_tb[KK*9];           // per-tap folded bias
__device__ __align__(16) float2 g_owp[C_*4*32];      // out weights packed [c][q][j]={ow[j][4c+q],ow[j+32][4c+q]}
__device__ __align__(16) float g_part[4*CGS28];      // partial logits (padded), 14.7 MB
__device__ __align__(16) float g_k[N_*HWD*KP];       // softmax weights (n,hd,wd,28)

// cp.async helpers
__device__ __forceinline__ void cp_async4(uint32_t dst_smem, const void* src, bool valid) {
    int sz = valid ? 4 : 0;
    asm volatile("cp.async.ca.shared.global [%0], [%1], 4, %2;\n"
                 :: "r"(dst_smem), "l"(src), "r"(sz));
}
__device__ __forceinline__ void cp_async8(uint32_t dst_smem, const void* src) {
    asm volatile("cp.async.ca.shared.global [%0], [%1], 8;\n"
                 :: "r"(dst_smem), "l"(src));
}
__device__ __forceinline__ void cp_async16z(uint32_t dst_smem, const void* src, bool valid) {
    int sz = valid ? 16 : 0;
    asm volatile("cp.async.ca.shared.global [%0], [%1], 16, %2;\n"
                 :: "r"(dst_smem), "l"(src), "r"(sz));
}
__device__ __forceinline__ void cp_async_commit() {
    asm volatile("cp.async.commit_group;\n");
}

// ---- packed fp32x2 helpers (sm_103a FFMA2; ptxas never auto-fuses) ----
__device__ __forceinline__ unsigned long long pack2(float lo, float hi) {
    unsigned long long r;
    asm("mov.b64 %0, {%1, %2};" : "=l"(r) : "f"(lo), "f"(hi));
    return r;
}
__device__ __forceinline__ void fma2(unsigned long long& d,
                                     unsigned long long a, unsigned long long b) {
    asm("fma.rn.f32x2 %0, %1, %2, %0;" : "+l"(d) : "l"(a), "l"(b));
}
__device__ __forceinline__ float2 unpack2(unsigned long long v) {
    float lo, hi;
    asm("mov.b64 {%0, %1}, %2;" : "=f"(lo), "=f"(hi) : "l"(v));
    return make_float2(lo, hi);
}

// ---------------------------------------------------------------------------
// Kernel 0: fold down(1x1) into enc(3x3). Also per-tap bias.
// ---------------------------------------------------------------------------
__global__ void k_w2(const float* __restrict__ ew,
                     const float* __restrict__ dw,
                     const float* __restrict__ db) {
    __shared__ float sew[576];
    __shared__ float sdb[64];
    __shared__ float sdw[64*64];
    const int kk = blockIdx.x;
    const int t  = threadIdx.x;
    sew[t] = ew[kk*576 + t];
    if (t < 64) sdb[t] = db[t];
    for (int i = t; i < 4096; i += 576) sdw[i] = dw[i];
    __syncthreads();

    const int ci = t / 9, rs = t % 9;
    float s = 0.f;
#pragma unroll 8
    for (int c = 0; c < 64; c++) s += sew[c*9 + rs] * sdw[c*64 + ci];
    g_w2d[(ci * KK + kk) * 9 + rs] = make_float2(s, s);   // per-channel contiguous

    if (t < 9) {
        float s2 = 0.f;
        for (int c = 0; c < 64; c++) s2 += sew[c*9 + t] * sdb[c];
        g_tb[kk*9 + t] = s2;
    }
}

// ---------------------------------------------------------------------------
// Kernel 0b: pack out-conv weights: g_owp[c][q][j] = {ow[j][4c+q], ow[j+32][4c+q]}
// ---------------------------------------------------------------------------
__global__ void k_owp(const float* __restrict__ ow) {
    const int c = blockIdx.x;        // 0..63
    const int t = threadIdx.x;       // 128: q = t>>5, j = t&31
    const int q = t >> 5, j = t & 31;
    g_owp[c * 128 + q * 32 + j] =
        make_float2(ow[j * 256 + c * 4 + q], ow[(j + 32) * 256 + c * 4 + q]);
}

// ---------------------------------------------------------------------------
// Kernel 1: folded 3x3 stride-2 conv x(64ch) -> 25 partial logits.
// (unchanged from R12)
// ---------------------------------------------------------------------------
#define ENC_TILE_F (33*36)

__global__ void __launch_bounds__(128) k_enc(const float* __restrict__ x) {
    __shared__ float  tile[2][33][36];         // 9504 B
    __shared__ float2 wsd[2][25][9];           // 3600 B, dup'd weights per channel
    const int n   = blockIdx.z >> 2;
    const int cg  = blockIdx.z & 3;
    const int hd0 = blockIdx.y * 16;
    const int wd0 = blockIdx.x * 16;
    const int tid = threadIdx.x;               // 128
    const int tx  = tid & 15;
    const int ty  = tid >> 4;                  // 0..7 -> hd pair
    const int c0  = cg * 16;

    const int h0 = 2 * hd0 - 1;
    const int w0 = 2 * wd0 - 1;
    const float* src = x + (size_t)n * C_ * HW;
    const uint32_t smem_tile = (uint32_t)__cvta_generic_to_shared(&tile[0][0][0]);
    const uint32_t smem_wsd  = (uint32_t)__cvta_generic_to_shared(&wsd[0][0][0]);

    auto stage = [&](int ci, int buf) {
        const float* sc = src + (size_t)(c0 + ci) * HW;
        const uint32_t tbase = smem_tile + (uint32_t)buf * (ENC_TILE_F * 4);
#pragma unroll
        for (int i = 0; i < 9; i++) {
            int idx = tid + i * 128;
            if (idx < 33*33) {
                int r = idx / 33, cc = idx % 33;
                int h = h0 + r, w = w0 + cc;
                bool ok = (h >= 0 && h < H_ && w >= 0 && w < W_);
                cp_async4(tbase + (uint32_t)(r * 36 + cc) * 4, sc + h * W_ + w, ok);
            }
        }
        const float2* wsrc = g_w2d + (size_t)(c0 + ci) * (KK * 9);
        const uint32_t wbase = smem_wsd + (uint32_t)buf * (KK * 9 * 8);
        cp_async8(wbase + (uint32_t)tid * 8, wsrc + tid);
        if (tid + 128 < 225)
            cp_async8(wbase + (uint32_t)(tid + 128) * 8, wsrc + tid + 128);
        cp_async_commit();
    };

    stage(0, 0);
    stage(1, 1);

    unsigned long long acc2[KK];               // {pixel(2ty), pixel(2ty+1)} packed
#pragma unroll
    for (int kk = 0; kk < KK; kk++) acc2[kk] = 0ULL;

    for (int ci = 0; ci < 16; ci++) {
        if (ci == 15) asm volatile("cp.async.wait_group 0;\n");
        else          asm volatile("cp.async.wait_group 1;\n");
        __syncthreads();

        const float (*tb)[36] = tile[ci & 1];
        unsigned long long v01[9];
#pragma unroll
        for (int r = 0; r < 3; r++)
#pragma unroll
            for (int s = 0; s < 3; s++)
                v01[r*3+s] = pack2(tb[4*ty + r][2*tx + s],
                                   tb[4*ty + 2 + r][2*tx + s]);

        const unsigned long long* wc =
            (const unsigned long long*)&wsd[ci & 1][0][0];
#pragma unroll
        for (int kk = 0; kk < KK; kk++)
#pragma unroll
            for (int t = 0; t < 9; t++)
                fma2(acc2[kk], wc[kk*9 + t], v01[t]);

        if (ci < 14) {
            __syncthreads();
            stage(ci + 2, ci & 1);
        }
    }

    const int wd = wd0 + tx;
    float* dst0 = g_part + cg * CGS28 + ((size_t)((n * HD + hd0 + 2*ty) * WD + wd)) * KP;
    float* dst1 = g_part + cg * CGS28 + ((size_t)((n * HD + hd0 + 2*ty + 1) * WD + wd)) * KP;
#pragma unroll
    for (int kk = 0; kk < KK; kk++) {
        float2 r = unpack2(acc2[kk]);
        dst0[kk] = r.x;
        dst1[kk] = r.y;
    }
}

// ---------------------------------------------------------------------------
// Kernel 2: sum 4 partials + bias (padding-aware tap bias) + softmax.
// ---------------------------------------------------------------------------
__global__ void __launch_bounds__(256) k_softmax(const float* __restrict__ eb) {
    __shared__ float stb[225];
    __shared__ float seb[25];
    const int tid = threadIdx.x;
    if (tid < 225) stb[tid] = g_tb[tid];
    if (tid < 25)  seb[tid] = eb[tid];
    __syncthreads();

    const int pix = blockIdx.x * 256 + tid;           // 32768 pixels
    const int wd = pix & 127;
    const int hd = (pix >> 7) & 127;

    const float r0 = (hd != 0) ? 1.f : 0.f;
    const float s0 = (wd != 0) ? 1.f : 0.f;
    float m9[9];
    m9[0] = r0 * s0; m9[1] = r0; m9[2] = r0;
    m9[3] = s0;      m9[4] = 1.f; m9[5] = 1.f;
    m9[6] = s0;      m9[7] = 1.f; m9[8] = 1.f;

    const float4* p0 = (const float4*)(g_part + (size_t)pix * KP);
    const float4* p1 = (const float4*)(g_part + CGS28   + (size_t)pix * KP);
    const float4* p2 = (const float4*)(g_part + 2*CGS28 + (size_t)pix * KP);
    const float4* p3 = (const float4*)(g_part + 3*CGS28 + (size_t)pix * KP);
    float a[28];
#pragma unroll
    for (int i = 0; i < 7; i++) {
        float4 v0 = p0[i], v1 = p1[i], v2 = p2[i], v3 = p3[i];
        a[4*i+0] = v0.x + v1.x + v2.x + v3.x;
        a[4*i+1] = v0.y + v1.y + v2.y + v3.y;
        a[4*i+2] = v0.z + v1.z + v2.z + v3.z;
        a[4*i+3] = v0.w + v1.w + v2.w + v3.w;
    }

    float lg[28];
#pragma unroll
    for (int kk = 0; kk < KK; kk++) {
        float v = a[kk] + seb[kk];
#pragma unroll
        for (int t = 0; t < 9; t++) v += m9[t] * stb[kk*9 + t];
        lg[kk] = v;
    }

    float mx = lg[0];
#pragma unroll
    for (int kk = 1; kk < KK; kk++) mx = fmaxf(mx, lg[kk]);
    float sum = 0.f;
#pragma unroll
    for (int kk = 0; kk < KK; kk++) { lg[kk] = expf(lg[kk] - mx); sum += lg[kk]; }
    float inv = 1.f / sum;
#pragma unroll
    for (int kk = 0; kk < KK; kk++) lg[kk] *= inv;
    lg[25] = 0.f; lg[26] = 0.f; lg[27] = 0.f;

    float4* dst = (float4*)(g_k + (size_t)pix * KP);
#pragma unroll
    for (int i = 0; i < 7; i++)
        dst[i] = make_float4(lg[4*i], lg[4*i+1], lg[4*i+2], lg[4*i+3]);
}

// ---------------------------------------------------------------------------
// Kernel 3: FUSED reassembly + 1x1 out-conv. Eliminates g_reasm (67MB traffic).
// Block = (b = hd>>1, n): 128 blocks x 256 threads.
//   thread pixel: hd = 2b + (tid>>7), wd = tid&127; col0 = 128*(hd&1)+wd = tid.
// Per channel c: stage band xs[q][r][272] (rows h=q*64+b-2+r, r=0..4; data at
// float offset 8, 16B cp.async, OOB rows zero-filled, +/-2 edges pre-zeroed),
// compute 4 quadrant reassembly values vq (kw in regs), accumulate 64 couts
// packed f32x2 via per-channel weight slices ows2 (LDS.128, broadcast).
//   out[co] = out_b[co] + sum_c sum_q ow[co][4c+q] * vq(c,q)
// ---------------------------------------------------------------------------
#define FB_ROW 272
#define FB_Q   (5*FB_ROW)          // 1360 floats
#define FB_BUF (4*FB_Q)            // 5440 floats per buffer
#define FB_SMEM (2*FB_BUF*4)       // 43,520 B dynamic

__global__ void __launch_bounds__(256) k_fuse(const float* __restrict__ x,
                                              const float* __restrict__ ob,
                                              float* __restrict__ out) {
    extern __shared__ float xs[];              // [2][FB_BUF]
    __shared__ float2 ows2[2][4][32];          // 2KB static, per-channel weight slice
    const int b   = blockIdx.x;                // hd pair: hd in {2b, 2b+1}
    const int n   = blockIdx.y;
    const int tid = threadIdx.x;               // 256

    const int ph = tid >> 7;                   // 0..1
    const int hd = 2 * b + ph;
    const int wd = tid & 127;

    const uint32_t xs_u32  = (uint32_t)__cvta_generic_to_shared(xs);
    const uint32_t ow_u32  = (uint32_t)__cvta_generic_to_shared(&ows2[0][0][0]);

    // zero-init both band buffers (edge zeros persist; cp.async covers [8,264))
    for (int i = tid; i < 2 * FB_BUF; i += 256) xs[i] = 0.f;

    // softmax weights for this pixel (7 LDG.128)
    float kw[25];
    {
        const float4* kp = (const float4*)(g_k + (size_t)((n * HD + hd) * WD + wd) * KP);
        float t28[28];
#pragma unroll
        for (int i = 0; i < 7; i++) {
            float4 v = kp[i];
            t28[4*i] = v.x; t28[4*i+1] = v.y; t28[4*i+2] = v.z; t28[4*i+3] = v.w;
        }
#pragma unroll
        for (int kk = 0; kk < KK; kk++) kw[kk] = t28[kk];
    }

    // cout accumulators: acc2[j] = {co=j, co=j+32}
    unsigned long long acc2[32];
#pragma unroll
    for (int j = 0; j < 32; j++) acc2[j] = pack2(ob[j], ob[j + 32]);

    const float* xn = x + (size_t)n * C_ * HW;
    const int q_of = tid >> 6;                 // 0..3: one quadrant row per 64 threads
    const int lane = tid & 63;                 // float4 within row

    __syncthreads();                           // zero-init visible before cp.async

    auto stage = [&](int c, int buf) {
        const float* src = xn + (size_t)c * HW;
        const uint32_t base = xs_u32 + (uint32_t)buf * (FB_BUF * 4);
#pragma unroll
        for (int r = 0; r < 5; r++) {
            const int h = q_of * 64 + b - 2 + r;
            const bool hv = (h >= 0) && (h < H_);
            cp_async16z(base + (uint32_t)((q_of * 5 + r) * FB_ROW + 8 + lane * 4) * 4,
                        src + h * W_ + lane * 4, hv);
        }
        if (tid < 64)
            asm volatile("cp.async.ca.shared.global [%0], [%1], 16;\n"
                         :: "r"(ow_u32 + (uint32_t)buf * 1024 + (uint32_t)tid * 16),
                            "l"((const char*)g_owp + (size_t)c * 1024 + (size_t)tid * 16));
        cp_async_commit();
    };

    stage(0, 0);
    stage(1, 1);

    for (int c = 0; c < 64; c++) {
        if (c == 63) asm volatile("cp.async.wait_group 0;\n");
        else         asm volatile("cp.async.wait_group 1;\n");
        __syncthreads();                       // buffer c&1 (band + weights) ready

        const float* xb = xs + (c & 1) * FB_BUF;

        // 4 quadrant reassembly values
        float vq[4];
#pragma unroll
        for (int q = 0; q < 4; q++) {
            const float* qb = xb + q * FB_Q + 6 + tid;   // col = 8 + (tid + dj - 2)
            float s = 0.f;
#pragma unroll
            for (int di = 0; di < 5; di++)
#pragma unroll
                for (int dj = 0; dj < 5; dj++)
                    s += kw[di * 5 + dj] * qb[di * FB_ROW + dj];
            vq[q] = s;
        }

        // cout GEMM update: 64 LDS.128 + 128 FFMA2
        const ulonglong2* wt = (const ulonglong2*)&ows2[c & 1][0][0];
#pragma unroll
        for (int q = 0; q < 4; q++) {
            unsigned long long v2 = pack2(vq[q], vq[q]);
#pragma unroll
            for (int jj = 0; jj < 16; jj++) {
                ulonglong2 wv = wt[q * 16 + jj];
                fma2(acc2[2*jj],     v2, wv.x);
                fma2(acc2[2*jj + 1], v2, wv.y);
            }
        }

        if (c < 62) {
            __syncthreads();                   // all reads of buffer c&1 done
            stage(c + 2, c & 1);
        }
    }

    // store: out[(n*64+co)*HWD + hd*WD + wd]; hd*WD+wd = b*256 + tid
    float* op = out + (size_t)n * 64 * HWD + (size_t)b * 256 + tid;
#pragma unroll
    for (int j = 0; j < 32; j++) {
        float2 r = unpack2(acc2[j]);
        op[(size_t)j * HWD]        = r.x;
        op[(size_t)(j + 32) * HWD] = r.y;
    }
}

// ---------------------------------------------------------------------------
extern "C" void kernel_launch(void* const* d_in, const int* in_sizes, int n_in,
                              void* d_out, int out_size) {
    const float* x      = (const float*)d_in[0];
    const float* down_w = (const float*)d_in[1];
    const float* down_b = (const float*)d_in[2];
    const float* enc_w  = (const float*)d_in[3];
    const float* enc_b  = (const float*)d_in[4];
    const float* out_w  = (const float*)d_in[5];
    const float* out_b  = (const float*)d_in[6];
    float* out = (float*)d_out;

    static bool attr_set = false;
    if (!attr_set) {
        cudaFuncSetAttribute(k_fuse, cudaFuncAttributeMaxDynamicSharedMemorySize,
                             FB_SMEM);
        attr_set = true;
    }

    k_w2<<<25, 576>>>(enc_w, down_w, down_b);
    k_owp<<<64, 128>>>(out_w);

    dim3 g1(8, 8, 8);                 // z = n*4 + channel-group
    k_enc<<<g1, 128>>>(x);

    k_softmax<<<128, 256>>>(enc_b);

    dim3 gf(64, 2);                   // (hd-pair, n) = 128 blocks
    k_fuse<<<gf, 256, FB_SMEM>>>(x, out_b, out);
}